// round 15
// baseline (speedup 1.0000x reference)
#include <cuda_runtime.h>
#include <cstddef>

// VolumeRenderer: weights[r,s] = alpha[r,s] * prod_{j<s}(1 - alpha[r,j] + 1e-10)
//                 rendered[r,c] = sum_s weights[r,s] * rgbs[r,s,c]
// d_out layout: [rendered R*3][weights R*128] (reference return order)
// Persistent grid-stride version: one wave of CTAs (152 SMs x 8), each warp
// loops over rays. Eliminates ~27 wave transitions of the flat launch.

#define FULL 0xffffffffu
#define S 128
#define EPS 1e-10f
#define NUM_SMS 152
#define CTAS_PER_SM 8

__global__ __launch_bounds__(256) void volrend_kernel(
    const float* __restrict__ alpha,
    const float* __restrict__ rgbs,
    float* __restrict__ out_rgb,   // [R,3]
    float* __restrict__ out_w,     // [R,128]
    int n_rays)
{
    const int lane    = threadIdx.x & 31;
    const int warp0   = (blockIdx.x * blockDim.x + threadIdx.x) >> 5;
    const int n_warps = (gridDim.x * blockDim.x) >> 5;

    for (int ray = warp0; ray < n_rays; ray += n_warps) {
        // ---- all global loads up front (4 LDG.128 in flight per lane) ----
        const float4* a4 = reinterpret_cast<const float4*>(alpha + (size_t)ray * S);
        const float4* r4 =
            reinterpret_cast<const float4*>(rgbs + (size_t)ray * (S * 3)) + lane * 3;
        const float4 a  = a4[lane];
        const float4 c0 = r4[0];
        const float4 c1 = r4[1];
        const float4 c2 = r4[2];

        const float t0 = 1.0f - a.x + EPS;
        const float t1 = 1.0f - a.y + EPS;
        const float t2 = 1.0f - a.z + EPS;
        const float t3 = 1.0f - a.w + EPS;

        // ---- multiplicative exclusive warp scan over per-lane products ----
        float scan = t0 * t1 * t2 * t3;
        #pragma unroll
        for (int o = 1; o < 32; o <<= 1) {
            float v = __shfl_up_sync(FULL, scan, o);
            if (lane >= o) scan *= v;
        }
        float prefix = __shfl_up_sync(FULL, scan, 1);
        if (lane == 0) prefix = 1.0f;

        // ---- per-lane sequential weights (matches reference ordering) ----
        float tr = prefix;
        const float w0 = tr * a.x; tr *= t0;
        const float w1 = tr * a.y; tr *= t1;
        const float w2 = tr * a.z; tr *= t2;
        const float w3 = tr * a.w;

        // ---- store weights (coalesced float4) ----
        reinterpret_cast<float4*>(out_w + (size_t)ray * S)[lane] =
            make_float4(w0, w1, w2, w3);

        // sample s0: (c0.x,c0.y,c0.z)  s1: (c0.w,c1.x,c1.y)
        // sample s2: (c1.z,c1.w,c2.x)  s3: (c2.y,c2.z,c2.w)
        float r = w0 * c0.x + w1 * c0.w + w2 * c1.z + w3 * c2.y;
        float g = w0 * c0.y + w1 * c1.x + w2 * c1.w + w3 * c2.z;
        float b = w0 * c0.z + w1 * c1.y + w2 * c2.x + w3 * c2.w;

        // ---- warp reduction ----
        #pragma unroll
        for (int o = 16; o > 0; o >>= 1) {
            r += __shfl_xor_sync(FULL, r, o);
            g += __shfl_xor_sync(FULL, g, o);
            b += __shfl_xor_sync(FULL, b, o);
        }
        if (lane == 0) {
            float* o = out_rgb + (size_t)ray * 3;
            o[0] = r; o[1] = g; o[2] = b;
        }
    }
}

extern "C" void kernel_launch(void* const* d_in, const int* in_sizes, int n_in,
                              void* d_out, int out_size)
{
    const float* alpha = (const float*)d_in[0];
    const float* rgbs  = (const float*)d_in[1];
    const int n_rays = in_sizes[0] / S;

    float* out_rgb = (float*)d_out;                       // R*3
    float* out_w   = (float*)d_out + (size_t)n_rays * 3;  // R*128

    const int threads = 256;                               // 8 warps per block
    int blocks = NUM_SMS * CTAS_PER_SM;                    // one full wave
    const int max_blocks = (n_rays + (threads / 32) - 1) / (threads / 32);
    if (blocks > max_blocks) blocks = max_blocks;
    volrend_kernel<<<blocks, threads>>>(alpha, rgbs, out_rgb, out_w, n_rays);
}

// round 16
// speedup vs baseline: 1.1047x; 1.1047x over previous
#include <cuda_runtime.h>
#include <cstddef>

// VolumeRenderer: weights[r,s] = alpha[r,s] * prod_{j<s}(1 - alpha[r,j] + 1e-10)
//                 rendered[r,c] = sum_s weights[r,s] * rgbs[r,s,c]
// d_out layout: [rendered R*3][weights R*128] (reference return order)
// Flat launch, one warp per ray (best measured config: 93.7us kernel, 88.4% DRAM).

#define FULL 0xffffffffu
#define S 128
#define EPS 1e-10f

__global__ __launch_bounds__(256) void volrend_kernel(
    const float* __restrict__ alpha,
    const float* __restrict__ rgbs,
    float* __restrict__ out_rgb,   // [R,3]
    float* __restrict__ out_w,     // [R,128]
    int n_rays)
{
    const int warp = (blockIdx.x * blockDim.x + threadIdx.x) >> 5;
    const int lane = threadIdx.x & 31;
    if (warp >= n_rays) return;

    // ---- load 4 alphas per lane (coalesced float4 across the warp) ----
    const float4* a4 = reinterpret_cast<const float4*>(alpha + (size_t)warp * S);
    const float4 a = a4[lane];

    const float t0 = 1.0f - a.x + EPS;
    const float t1 = 1.0f - a.y + EPS;
    const float t2 = 1.0f - a.z + EPS;
    const float t3 = 1.0f - a.w + EPS;

    // ---- multiplicative exclusive warp scan over per-lane products ----
    float scan = t0 * t1 * t2 * t3;
    #pragma unroll
    for (int o = 1; o < 32; o <<= 1) {
        float v = __shfl_up_sync(FULL, scan, o);
        if (lane >= o) scan *= v;
    }
    float prefix = __shfl_up_sync(FULL, scan, 1);
    if (lane == 0) prefix = 1.0f;

    // ---- per-lane sequential weights (matches reference ordering) ----
    float tr = prefix;
    const float w0 = tr * a.x; tr *= t0;
    const float w1 = tr * a.y; tr *= t1;
    const float w2 = tr * a.z; tr *= t2;
    const float w3 = tr * a.w;

    // ---- store weights (coalesced float4) ----
    reinterpret_cast<float4*>(out_w + (size_t)warp * S)[lane] =
        make_float4(w0, w1, w2, w3);

    // ---- load 12 rgb floats for this lane's 4 samples: 3x float4, coalesced ----
    const float4* r4 =
        reinterpret_cast<const float4*>(rgbs + (size_t)warp * (S * 3)) + lane * 3;
    const float4 c0 = r4[0];
    const float4 c1 = r4[1];
    const float4 c2 = r4[2];
    // sample s0: (c0.x,c0.y,c0.z)  s1: (c0.w,c1.x,c1.y)
    // sample s2: (c1.z,c1.w,c2.x)  s3: (c2.y,c2.z,c2.w)
    float r = w0 * c0.x + w1 * c0.w + w2 * c1.z + w3 * c2.y;
    float g = w0 * c0.y + w1 * c1.x + w2 * c1.w + w3 * c2.z;
    float b = w0 * c0.z + w1 * c1.y + w2 * c2.x + w3 * c2.w;

    // ---- warp butterfly reduction: every lane ends with the full sums ----
    #pragma unroll
    for (int o = 16; o > 0; o >>= 1) {
        r += __shfl_xor_sync(FULL, r, o);
        g += __shfl_xor_sync(FULL, g, o);
        b += __shfl_xor_sync(FULL, b, o);
    }

    // ---- lanes 0..2 each write one channel: single 12B coalesced run ----
    if (lane < 3) {
        const float v = (lane == 0) ? r : (lane == 1) ? g : b;
        out_rgb[(size_t)warp * 3 + lane] = v;
    }
}

extern "C" void kernel_launch(void* const* d_in, const int* in_sizes, int n_in,
                              void* d_out, int out_size)
{
    const float* alpha = (const float*)d_in[0];
    const float* rgbs  = (const float*)d_in[1];
    const int n_rays = in_sizes[0] / S;

    float* out_rgb = (float*)d_out;                       // R*3
    float* out_w   = (float*)d_out + (size_t)n_rays * 3;  // R*128

    const int threads = 256;              // 8 warps = 8 rays per block
    const int rays_per_block = threads / 32;
    const int blocks = (n_rays + rays_per_block - 1) / rays_per_block;
    volrend_kernel<<<blocks, threads>>>(alpha, rgbs, out_rgb, out_w, n_rays);
}

// round 17
// speedup vs baseline: 1.6095x; 1.4569x over previous
#include <cuda_runtime.h>
#include <cstddef>

// VolumeRenderer: weights[r,s] = alpha[r,s] * prod_{j<s}(1 - alpha[r,j] + 1e-10)
//                 rendered[r,c] = sum_s weights[r,s] * rgbs[r,s,c]
// d_out layout: [rendered R*3][weights R*128] (reference return order)
//
// Early-ray-termination: lanes whose incoming transmittance (scan prefix) is
// below 1e-9 skip their rgb loads entirely — their samples' contribution to
// the rendered sum is bounded by 4*1e-9 per lane (<1.3e-7 total absolute),
// vastly below both fp32 resolution of the O(0.5) result and the 1e-3
// tolerance. Weights are still computed and stored for ALL samples.
// Cuts rgbs read traffic from 384 MiB to ~85 MiB (expected ~7/32 lanes active).

#define FULL 0xffffffffu
#define S 128
#define EPS 1e-10f
#define TERM_THRESH 1e-9f

__global__ __launch_bounds__(256) void volrend_kernel(
    const float* __restrict__ alpha,
    const float* __restrict__ rgbs,
    float* __restrict__ out_rgb,   // [R,3]
    float* __restrict__ out_w,     // [R,128]
    int n_rays)
{
    const int warp = (blockIdx.x * blockDim.x + threadIdx.x) >> 5;
    const int lane = threadIdx.x & 31;
    if (warp >= n_rays) return;

    // ---- load 4 alphas per lane (coalesced float4 across the warp) ----
    const float4* a4 = reinterpret_cast<const float4*>(alpha + (size_t)warp * S);
    const float4 a = a4[lane];

    const float t0 = 1.0f - a.x + EPS;
    const float t1 = 1.0f - a.y + EPS;
    const float t2 = 1.0f - a.z + EPS;
    const float t3 = 1.0f - a.w + EPS;

    // ---- multiplicative exclusive warp scan over per-lane products ----
    float scan = t0 * t1 * t2 * t3;
    #pragma unroll
    for (int o = 1; o < 32; o <<= 1) {
        float v = __shfl_up_sync(FULL, scan, o);
        if (lane >= o) scan *= v;
    }
    float prefix = __shfl_up_sync(FULL, scan, 1);
    if (lane == 0) prefix = 1.0f;

    // ---- per-lane sequential weights (matches reference ordering) ----
    float tr = prefix;
    const float w0 = tr * a.x; tr *= t0;
    const float w1 = tr * a.y; tr *= t1;
    const float w2 = tr * a.z; tr *= t2;
    const float w3 = tr * a.w;

    // ---- store weights (coalesced float4) — required for all samples ----
    reinterpret_cast<float4*>(out_w + (size_t)warp * S)[lane] =
        make_float4(w0, w1, w2, w3);

    // ---- early termination: only lanes with non-negligible transmittance
    //      read their rgb samples (contiguous low lanes -> still coalesced) ----
    float r = 0.f, g = 0.f, b = 0.f;
    if (prefix >= TERM_THRESH) {
        const float4* r4 =
            reinterpret_cast<const float4*>(rgbs + (size_t)warp * (S * 3)) + lane * 3;
        const float4 c0 = r4[0];
        const float4 c1 = r4[1];
        const float4 c2 = r4[2];
        // sample s0: (c0.x,c0.y,c0.z)  s1: (c0.w,c1.x,c1.y)
        // sample s2: (c1.z,c1.w,c2.x)  s3: (c2.y,c2.z,c2.w)
        r = w0 * c0.x + w1 * c0.w + w2 * c1.z + w3 * c2.y;
        g = w0 * c0.y + w1 * c1.x + w2 * c1.w + w3 * c2.z;
        b = w0 * c0.z + w1 * c1.y + w2 * c2.x + w3 * c2.w;
    }

    // ---- warp butterfly reduction: every lane ends with the full sums ----
    #pragma unroll
    for (int o = 16; o > 0; o >>= 1) {
        r += __shfl_xor_sync(FULL, r, o);
        g += __shfl_xor_sync(FULL, g, o);
        b += __shfl_xor_sync(FULL, b, o);
    }

    // ---- lanes 0..2 each write one channel: single 12B coalesced run ----
    if (lane < 3) {
        const float v = (lane == 0) ? r : (lane == 1) ? g : b;
        out_rgb[(size_t)warp * 3 + lane] = v;
    }
}

extern "C" void kernel_launch(void* const* d_in, const int* in_sizes, int n_in,
                              void* d_out, int out_size)
{
    const float* alpha = (const float*)d_in[0];
    const float* rgbs  = (const float*)d_in[1];
    const int n_rays = in_sizes[0] / S;

    float* out_rgb = (float*)d_out;                       // R*3
    float* out_w   = (float*)d_out + (size_t)n_rays * 3;  // R*128

    const int threads = 256;              // 8 warps = 8 rays per block
    const int rays_per_block = threads / 32;
    const int blocks = (n_rays + rays_per_block - 1) / rays_per_block;
    volrend_kernel<<<blocks, threads>>>(alpha, rgbs, out_rgb, out_w, n_rays);
}